// round 1
// baseline (speedup 1.0000x reference)
#include <cuda_runtime.h>
#include <math.h>

#define N      8192
#define NFEAT  256
#define NHID   64
#define NHEADS 4
#define NCLASS 121
#define DCAT   256   // NHEADS*NHID
#define CAP    768   // max neighbors per row (mean ~82, sigma ~9)

// ---------------- scratch (static __device__, no allocs) ----------------
__device__ __align__(16) float g_Wh[(size_t)N * DCAT];     // layer1 Wh, head-concat layout
__device__ float g_fsrc1[NHEADS * N];
__device__ float g_fdst1[NHEADS * N];
__device__ __align__(16) float g_h1[(size_t)N * DCAT];     // layer1 output (h_cat)
__device__ __align__(16) float g_Wh2[(size_t)N * NCLASS];  // layer2 Wh
__device__ float g_fs2[N];
__device__ float g_fd2[N];
__device__ int   g_nbr[(size_t)N * CAP];                   // CSR neighbor lists
__device__ int   g_cnt[N];

// ---------------- K0: Wh_all[n, h*64+d] = x @ Ws[h] ----------------
__global__ void __launch_bounds__(256) k0_gemm(const float* __restrict__ x,
                                               const float* __restrict__ Ws) {
    __shared__ float xs[64][65];
    __shared__ float ws[64][64];
    const int h    = blockIdx.y;
    const int row0 = blockIdx.x * 64;
    const int t    = threadIdx.x;
    const int tx   = t & 15, ty = t >> 4;
    float acc[4][4] = {};
    const float* Wb = Ws + (size_t)h * NFEAT * NHID;
    for (int k0 = 0; k0 < NFEAT; k0 += 64) {
        for (int idx = t; idx < 64 * 64; idx += 256) {
            int r = idx >> 6, c = idx & 63;
            xs[r][c] = x[(size_t)(row0 + r) * NFEAT + k0 + c];
            ws[r][c] = Wb[(size_t)(k0 + r) * NHID + c];
        }
        __syncthreads();
        #pragma unroll 16
        for (int kk = 0; kk < 64; kk++) {
            float a[4], b[4];
            #pragma unroll
            for (int i = 0; i < 4; i++) a[i] = xs[ty * 4 + i][kk];
            #pragma unroll
            for (int j = 0; j < 4; j++) b[j] = ws[kk][tx * 4 + j];
            #pragma unroll
            for (int i = 0; i < 4; i++)
                #pragma unroll
                for (int j = 0; j < 4; j++)
                    acc[i][j] += a[i] * b[j];
        }
        __syncthreads();
    }
    #pragma unroll
    for (int i = 0; i < 4; i++)
        #pragma unroll
        for (int j = 0; j < 4; j++)
            g_Wh[(size_t)(row0 + ty * 4 + i) * DCAT + h * 64 + tx * 4 + j] = acc[i][j];
}

// ---------------- K0b: f_src/f_dst for layer 1 (one warp per (n,h)) ----------------
__global__ void k0b_f(const float* __restrict__ a_heads) {
    int gw   = (blockIdx.x * blockDim.x + threadIdx.x) >> 5;
    int lane = threadIdx.x & 31;
    if (gw >= N * NHEADS) return;
    int n = gw >> 2, h = gw & 3;
    const float* wh = g_Wh + (size_t)n * DCAT + h * 64;
    const float* as = a_heads + h * 2 * NHID;
    float v0 = wh[lane], v1 = wh[lane + 32];
    float s = v0 * as[lane]      + v1 * as[lane + 32];
    float d = v0 * as[64 + lane] + v1 * as[96 + lane];
    #pragma unroll
    for (int o = 16; o; o >>= 1) {
        s += __shfl_down_sync(~0u, s, o);
        d += __shfl_down_sync(~0u, d, o);
    }
    if (lane == 0) { g_fsrc1[h * N + n] = s; g_fdst1[h * N + n] = d; }
}

// ---------------- K1: layer1 sparse attention + aggregation (1 block / row) ----------------
__global__ void __launch_bounds__(256) k1_attn(const float* __restrict__ adj) {
    const int i = blockIdx.x;
    const int t = threadIdx.x;
    const int lane = t & 31, warp = t >> 5;

    __shared__ int   s_nbr[CAP];
    __shared__ float s_p[CAP][NHEADS];
    __shared__ int   s_wcnt[8];
    __shared__ float s_wred[8][NHEADS];
    __shared__ float s_m[NHEADS], s_sum[NHEADS];

    // ---- Phase A: deterministic stream-compaction of adj row (float4, ballot+scan) ----
    const float4* arow4 = (const float4*)(adj + (size_t)i * N);
    int total = 0;
    #pragma unroll 1
    for (int base = 0; base < N / 4; base += 256) {
        float4 v = __ldcs(&arow4[base + t]);    // streaming: evict-first, keep L2 for Wh
        int j0 = (base + t) * 4;
        unsigned pm = (v.x > 0.f ? 1u : 0u) | (v.y > 0.f ? 2u : 0u)
                    | (v.z > 0.f ? 4u : 0u) | (v.w > 0.f ? 8u : 0u);
        int cnt = __popc(pm);
        int sc = cnt;                           // warp inclusive scan
        #pragma unroll
        for (int o = 1; o < 32; o <<= 1) {
            int u = __shfl_up_sync(~0u, sc, o);
            if (lane >= o) sc += u;
        }
        if (lane == 31) s_wcnt[warp] = sc;
        __syncthreads();
        int off = total + (sc - cnt);
        for (int w = 0; w < warp; w++) off += s_wcnt[w];
        int p = off;
        if (pm & 1) { if (p < CAP) s_nbr[p] = j0;     p++; }
        if (pm & 2) { if (p < CAP) s_nbr[p] = j0 + 1; p++; }
        if (pm & 4) { if (p < CAP) s_nbr[p] = j0 + 2; p++; }
        if (pm & 8) { if (p < CAP) s_nbr[p] = j0 + 3; p++; }
        int chunk = 0;
        #pragma unroll
        for (int w = 0; w < 8; w++) chunk += s_wcnt[w];
        total += chunk;
        __syncthreads();
    }
    const int nn = min(total, CAP);
    if (t == 0) g_cnt[i] = nn;
    for (int jl = t; jl < nn; jl += 256) g_nbr[(size_t)i * CAP + jl] = s_nbr[jl];

    // ---- Phase B: e = lrelu(f_src[i] + f_dst[j]); row-max per head ----
    float fs[NHEADS];
    #pragma unroll
    for (int h = 0; h < NHEADS; h++) fs[h] = g_fsrc1[h * N + i];
    float mloc[NHEADS];
    #pragma unroll
    for (int h = 0; h < NHEADS; h++) mloc[h] = -3.4e38f;
    for (int jl = t; jl < nn; jl += 256) {
        int j = s_nbr[jl];
        #pragma unroll
        for (int h = 0; h < NHEADS; h++) {
            float e = fs[h] + g_fdst1[h * N + j];
            e = e > 0.f ? e : 0.2f * e;
            s_p[jl][h] = e;
            mloc[h] = fmaxf(mloc[h], e);
        }
    }
    #pragma unroll
    for (int h = 0; h < NHEADS; h++)
        #pragma unroll
        for (int o = 16; o; o >>= 1)
            mloc[h] = fmaxf(mloc[h], __shfl_xor_sync(~0u, mloc[h], o));
    if (lane == 0)
        #pragma unroll
        for (int h = 0; h < NHEADS; h++) s_wred[warp][h] = mloc[h];
    __syncthreads();
    if (t < NHEADS) {
        float m = s_wred[0][t];
        #pragma unroll
        for (int w = 1; w < 8; w++) m = fmaxf(m, s_wred[w][t]);
        s_m[t] = m;
    }
    __syncthreads();

    // ---- exp + sum ----
    float sloc[NHEADS] = {0.f, 0.f, 0.f, 0.f};
    for (int jl = t; jl < nn; jl += 256) {
        #pragma unroll
        for (int h = 0; h < NHEADS; h++) {
            float p = __expf(s_p[jl][h] - s_m[h]);
            s_p[jl][h] = p;
            sloc[h] += p;
        }
    }
    #pragma unroll
    for (int h = 0; h < NHEADS; h++)
        #pragma unroll
        for (int o = 16; o; o >>= 1)
            sloc[h] += __shfl_xor_sync(~0u, sloc[h], o);
    if (lane == 0)
        #pragma unroll
        for (int h = 0; h < NHEADS; h++) s_wred[warp][h] = sloc[h];
    __syncthreads();
    if (t < NHEADS) {
        float s = 0.f;
        #pragma unroll
        for (int w = 0; w < 8; w++) s += s_wred[w][t];
        s_sum[t] = s;
    }
    __syncthreads();

    // ---- aggregation: thread t owns output dim t; head = t>>6 ----
    const int h = t >> 6;
    float acc = 0.f;
    int jl = 0;
    for (; jl + 4 <= nn; jl += 4) {
        int j0 = s_nbr[jl], j1 = s_nbr[jl + 1], j2 = s_nbr[jl + 2], j3 = s_nbr[jl + 3];
        float w0 = s_p[jl][h], w1 = s_p[jl + 1][h], w2 = s_p[jl + 2][h], w3 = s_p[jl + 3][h];
        acc += w0 * g_Wh[(size_t)j0 * DCAT + t];
        acc += w1 * g_Wh[(size_t)j1 * DCAT + t];
        acc += w2 * g_Wh[(size_t)j2 * DCAT + t];
        acc += w3 * g_Wh[(size_t)j3 * DCAT + t];
    }
    for (; jl < nn; jl++)
        acc += s_p[jl][h] * g_Wh[(size_t)s_nbr[jl] * DCAT + t];
    float v = acc / s_sum[h];
    g_h1[(size_t)i * DCAT + t] = v > 0.f ? v : expm1f(v);   // ELU (alpha=1)
}

// ---------------- K2: Wh2 = h_cat @ W_out  (16 rows / block) ----------------
__global__ void __launch_bounds__(128) k2_gemm(const float* __restrict__ W_out) {
    __shared__ float hs[16][NFEAT];
    const int row0 = blockIdx.x * 16;
    const int t = threadIdx.x;
    const float4* src = (const float4*)(g_h1 + (size_t)row0 * DCAT);
    float4* dst4 = (float4*)(&hs[0][0]);
    for (int idx = t; idx < 16 * (NFEAT / 4); idx += 128) dst4[idx] = src[idx];
    __syncthreads();
    if (t < NCLASS) {
        float acc[16] = {};
        for (int k = 0; k < NFEAT; k++) {
            float w = W_out[(size_t)k * NCLASS + t];
            #pragma unroll
            for (int r = 0; r < 16; r++) acc[r] += hs[r][k] * w;
        }
        #pragma unroll
        for (int r = 0; r < 16; r++)
            g_Wh2[(size_t)(row0 + r) * NCLASS + t] = acc[r];
    }
}

// ---------------- K2b: f_src/f_dst for output layer (one warp per row) ----------------
__global__ void k2b_f(const float* __restrict__ a_out) {
    int gw   = (blockIdx.x * blockDim.x + threadIdx.x) >> 5;
    int lane = threadIdx.x & 31;
    if (gw >= N) return;
    const float* w = g_Wh2 + (size_t)gw * NCLASS;
    float s = 0.f, d = 0.f;
    for (int c = lane; c < NCLASS; c += 32) {
        float v = w[c];
        s += v * a_out[c];
        d += v * a_out[NCLASS + c];
    }
    #pragma unroll
    for (int o = 16; o; o >>= 1) {
        s += __shfl_down_sync(~0u, s, o);
        d += __shfl_down_sync(~0u, d, o);
    }
    if (!lane) { g_fs2[gw] = s; g_fd2[gw] = d; }
}

// ---------------- K3: output-layer attention (1 block / row, reuses CSR) ----------------
__global__ void __launch_bounds__(128) k3_attn(float* __restrict__ out) {
    const int i = blockIdx.x;
    const int t = threadIdx.x;
    const int lane = t & 31, warp = t >> 5;
    __shared__ int   s_nbr[CAP];
    __shared__ float s_p[CAP];
    __shared__ float s_red[4];
    __shared__ float s_m, s_s;

    const int nn = g_cnt[i];
    const int* nb = g_nbr + (size_t)i * CAP;
    for (int jl = t; jl < nn; jl += 128) s_nbr[jl] = nb[jl];
    __syncthreads();

    const float fs = g_fs2[i];
    float mloc = -3.4e38f;
    for (int jl = t; jl < nn; jl += 128) {
        float e = fs + g_fd2[s_nbr[jl]];
        e = e > 0.f ? e : 0.2f * e;
        s_p[jl] = e;
        mloc = fmaxf(mloc, e);
    }
    #pragma unroll
    for (int o = 16; o; o >>= 1) mloc = fmaxf(mloc, __shfl_xor_sync(~0u, mloc, o));
    if (!lane) s_red[warp] = mloc;
    __syncthreads();
    if (t == 0) {
        float m = s_red[0];
        #pragma unroll
        for (int w = 1; w < 4; w++) m = fmaxf(m, s_red[w]);
        s_m = m;
    }
    __syncthreads();
    const float m = s_m;
    float sloc = 0.f;
    for (int jl = t; jl < nn; jl += 128) {
        float p = __expf(s_p[jl] - m);
        s_p[jl] = p;
        sloc += p;
    }
    #pragma unroll
    for (int o = 16; o; o >>= 1) sloc += __shfl_xor_sync(~0u, sloc, o);
    if (!lane) s_red[warp] = sloc;
    __syncthreads();
    if (t == 0) {
        float s = 0.f;
        #pragma unroll
        for (int w = 0; w < 4; w++) s += s_red[w];
        s_s = s;
    }
    __syncthreads();

    if (t < NCLASS) {
        float acc = 0.f;
        int jl = 0;
        for (; jl + 4 <= nn; jl += 4) {
            acc += s_p[jl]     * g_Wh2[(size_t)s_nbr[jl]     * NCLASS + t];
            acc += s_p[jl + 1] * g_Wh2[(size_t)s_nbr[jl + 1] * NCLASS + t];
            acc += s_p[jl + 2] * g_Wh2[(size_t)s_nbr[jl + 2] * NCLASS + t];
            acc += s_p[jl + 3] * g_Wh2[(size_t)s_nbr[jl + 3] * NCLASS + t];
        }
        for (; jl < nn; jl++)
            acc += s_p[jl] * g_Wh2[(size_t)s_nbr[jl] * NCLASS + t];
        out[(size_t)i * NCLASS + t] = acc / s_s;   // concat=False: raw aggregation
    }
}

// ---------------- launcher ----------------
extern "C" void kernel_launch(void* const* d_in, const int* in_sizes, int n_in,
                              void* d_out, int out_size) {
    const float* x       = (const float*)d_in[0];
    const float* adj     = (const float*)d_in[1];
    const float* Ws      = (const float*)d_in[2];
    const float* a_heads = (const float*)d_in[3];
    const float* W_out   = (const float*)d_in[4];
    const float* a_out   = (const float*)d_in[5];
    float* out = (float*)d_out;

    k0_gemm<<<dim3(N / 64, NHEADS), 256>>>(x, Ws);
    k0b_f<<<(N * NHEADS) / 8, 256>>>(a_heads);
    k1_attn<<<N, 256>>>(adj);
    k2_gemm<<<N / 16, 128>>>(W_out);
    k2b_f<<<N / 8, 256>>>(a_out);
    k3_attn<<<N, 128>>>(out);
}